// round 15
// baseline (speedup 1.0000x reference)
#include <cuda_runtime.h>
#include <cuda_bf16.h>
#include <math.h>
#include <stdint.h>

// ---------------- problem constants ----------------
#define NB     256
#define CC     128
#define HH     77
#define WW     44
#define PP     7
#define MAXH   11
#define POSEC  256
#define VV     17
#define OUTC   512
#define DEPTH  4
#define HEADS  8
#define DHEAD  64
#define FFH    1024
#define FUSED  1920
#define TOK    (NB*PP)       // 1792

// ---------------- scratch (static device memory; no allocation) ----------------
__device__ float g_X0[TOK * FUSED];
__device__ float g_Xn[TOK * FUSED];
__device__ float g_fuse[TOK * OUTC];
__device__ float g_qkv[TOK * 3 * OUTC];
__device__ float g_ao[TOK * OUTC];
__device__ float g_ff[TOK * FFH];
__device__ float g_part[2 * TOK * OUTC];   // split-K partials
// tf32-pre-rounded weights
__device__ float g_We[FUSED * OUTC];
__device__ float g_Wqkv[DEPTH * OUTC * 3 * OUTC];
__device__ float g_Wo[DEPTH * OUTC * OUTC];
__device__ float g_W1[DEPTH * OUTC * FFH];
__device__ float g_W2[DEPTH * FFH * OUTC];

__device__ __forceinline__ uint32_t f2tf32(float f) {
    uint32_t u;
    asm("cvt.rna.tf32.f32 %0, %1;" : "=r"(u) : "f"(f));
    return u;
}
__device__ __forceinline__ float roundtf(float f) { return __uint_as_float(f2tf32(f)); }

// ---------------- 0) weight pre-rounding ----------------
__global__ void round_tf32_kernel(const float* __restrict__ in, float* __restrict__ out, int n4) {
    int i = blockIdx.x * blockDim.x + threadIdx.x;
    if (i >= n4) return;
    float4 v = ((const float4*)in)[i];
    v.x = roundtf(v.x); v.y = roundtf(v.y); v.z = roundtf(v.z); v.w = roundtf(v.w);
    ((float4*)out)[i] = v;
}

// ---------------- 1) silhouette pooling: warp per row, 8 rows/warp ----------------
// Coalesced lane-parallel read over W (3 wavefronts/row vs 11 serialized),
// butterfly reduce. Grid = R/64 CTAs (moderate dispatch cost).
__global__ void pool_kernel(const float* __restrict__ sil, const int* __restrict__ mins,
                            float* __restrict__ X0) {
    const int R = NB * PP * CC * MAXH;           // 2,523,136 (divisible by 64)
    int wg   = blockIdx.x * 8 + (threadIdx.x >> 5);
    int lane = threadIdx.x & 31;
    int row0 = wg * 8;
#pragma unroll
    for (int k = 0; k < 8; k++) {
        int gw = row0 + k;
        if (gw >= R) return;
        int hl = gw % MAXH;
        int c  = (gw / MAXH) % CC;
        int p  = (gw / (MAXH * CC)) % PP;
        int n  = gw / (MAXH * CC * PP);
        int start = mins[p * NB + n];
        start = min(max(start, 0), HH - MAXH);
        const float* row = sil + (((size_t)n * CC + c) * HH + start + hl) * WW;
        float v1 = row[lane];
        bool act2 = lane < (WW - 32);            // lanes 0..11
        float v2 = act2 ? row[32 + lane] : -3.4e38f;
        float s  = v1 + (act2 ? v2 : 0.0f);
        float mx = fmaxf(v1, v2);
#pragma unroll
        for (int o = 16; o > 0; o >>= 1) {
            s  += __shfl_xor_sync(0xFFFFFFFFu, s, o);
            mx = fmaxf(mx, __shfl_xor_sync(0xFFFFFFFFu, mx, o));
        }
        if (lane == 0)
            X0[((size_t)(n * PP + p)) * FUSED + c * MAXH + hl] = s * (1.0f / WW) + mx;
    }
}

// ---------------- 2) pose binning + leaky relu ----------------
__global__ void pose_kernel(const float* __restrict__ pose, float* __restrict__ X0) {
    int idx = blockIdx.x * blockDim.x + threadIdx.x;
    const int total = NB * PP * POSEC * 2;
    if (idx >= total) return;
    int b  = idx & 1;
    int pc = (idx >> 1) & (POSEC - 1);
    int p  = (idx >> 9) % PP;
    int n  = idx / (PP * POSEC * 2);
    const float* pp = pose + ((size_t)n * POSEC + pc) * VV;
    float v;
    if (p == 0) {
        v = (b == 0) ? (pp[0] + pp[1] + pp[2]) * (1.0f / 3.0f)
                     : (pp[2] + pp[3] + pp[4]) * (1.0f / 3.0f);
    } else {
        v = pp[3 + 2 * p + b];
    }
    v = (v >= 0.0f) ? v : 0.01f * v;
    X0[((size_t)(n * PP + p)) * FUSED + CC * MAXH + pc * 2 + b] = v;
}

// ---------------- 3) LayerNorm (block per row); ROUND pre-rounds output to tf32 ----------------
template <int D, bool ROUND>
__global__ void ln_kernel(const float* __restrict__ X, float* __restrict__ Y,
                          const float* __restrict__ g, const float* __restrict__ b) {
    constexpr int NT = 256;
    constexpr int NE = (D + NT - 1) / NT;
    int row = blockIdx.x;
    const float* x = X + (size_t)row * D;
    float* y = Y + (size_t)row * D;
    int t = threadIdx.x;
    float vals[NE];
    float s = 0.0f, s2 = 0.0f;
#pragma unroll
    for (int e = 0; e < NE; e++) {
        int i = t + e * NT;
        float v = (i < D) ? x[i] : 0.0f;
        vals[e] = v;
        s += v; s2 += v * v;
    }
#pragma unroll
    for (int o = 16; o > 0; o >>= 1) {
        s  += __shfl_xor_sync(0xFFFFFFFFu, s, o);
        s2 += __shfl_xor_sync(0xFFFFFFFFu, s2, o);
    }
    __shared__ float sh[20];
    int wid = t >> 5, lid = t & 31;
    if (lid == 0) { sh[wid] = s; sh[8 + wid] = s2; }
    __syncthreads();
    if (t == 0) {
        float ts = 0.0f, ts2 = 0.0f;
#pragma unroll
        for (int w = 0; w < NT / 32; w++) { ts += sh[w]; ts2 += sh[8 + w]; }
        float m = ts / D;
        float var = ts2 / D - m * m;
        sh[16] = m;
        sh[17] = rsqrtf(var + 1e-5f);
    }
    __syncthreads();
    float m = sh[16], r = sh[17];
#pragma unroll
    for (int e = 0; e < NE; e++) {
        int i = t + e * NT;
        if (i < D) {
            float v = (vals[e] - m) * r * g[i] + b[i];
            y[i] = ROUND ? roundtf(v) : v;
        }
    }
}

// ---------------- 3b) split-K combine + LayerNorm (D = OUTC) ----------------
template <bool HASRES, bool NORMFUSE>
__global__ void ln_combine_kernel(const float* __restrict__ P,
                                  const float* __restrict__ bias,
                                  const float* __restrict__ res,
                                  float* __restrict__ fuse, float* __restrict__ Y,
                                  const float* __restrict__ g, const float* __restrict__ b) {
    constexpr int D = OUTC, NT = 256, NE = 2;
    int row = blockIdx.x;
    const float* p0 = P + (size_t)row * D;
    const float* p1 = P + (size_t)TOK * D + (size_t)row * D;
    int t = threadIdx.x;
    float vals[NE];
    float s = 0.0f, s2 = 0.0f;
#pragma unroll
    for (int e = 0; e < NE; e++) {
        int i = t + e * NT;
        float v = p0[i] + p1[i] + bias[i];
        if (HASRES) v += res[(size_t)row * D + i];
        vals[e] = v;
        s += v; s2 += v * v;
    }
#pragma unroll
    for (int o = 16; o > 0; o >>= 1) {
        s  += __shfl_xor_sync(0xFFFFFFFFu, s, o);
        s2 += __shfl_xor_sync(0xFFFFFFFFu, s2, o);
    }
    __shared__ float sh[20];
    int wid = t >> 5, lid = t & 31;
    if (lid == 0) { sh[wid] = s; sh[8 + wid] = s2; }
    __syncthreads();
    if (t == 0) {
        float ts = 0.0f, ts2 = 0.0f;
#pragma unroll
        for (int w = 0; w < NT / 32; w++) { ts += sh[w]; ts2 += sh[8 + w]; }
        float m = ts / D;
        float var = ts2 / D - m * m;
        sh[16] = m;
        sh[17] = rsqrtf(var + 1e-5f);
    }
    __syncthreads();
    float m = sh[16], r = sh[17];
#pragma unroll
    for (int e = 0; e < NE; e++) {
        int i = t + e * NT;
        float nv = (vals[e] - m) * r * g[i] + b[i];
        if (NORMFUSE) {
            fuse[(size_t)row * D + i] = nv;
        } else {
            fuse[(size_t)row * D + i] = vals[e];
            Y[(size_t)row * D + i]    = roundtf(nv);
        }
    }
}

// ---------------- 3c) final combine: out = P0 + P1 + bias + fuse ----------------
__global__ void final_combine_kernel(const float* __restrict__ P,
                                     const float* __restrict__ bias,
                                     const float* __restrict__ fuse,
                                     float* __restrict__ out) {
    int i4 = blockIdx.x * blockDim.x + threadIdx.x;
    const int total4 = TOK * OUTC / 4;
    if (i4 >= total4) return;
    float4 a = ((const float4*)P)[i4];
    float4 c = ((const float4*)(P + (size_t)TOK * OUTC))[i4];
    float4 f = ((const float4*)fuse)[i4];
    const float4 bb = ((const float4*)bias)[i4 & (OUTC / 4 - 1)];
    float4 o;
    o.x = a.x + c.x + bb.x + f.x;
    o.y = a.y + c.y + bb.y + f.y;
    o.z = a.z + c.z + bb.z + f.z;
    o.w = a.w + c.w + bb.w + f.w;
    ((float4*)out)[i4] = o;
}

// ---------------- 4) tf32 tensor-core GEMM (round-11 core) ----------------
// BM=64, BN=64, BK=32, 128 threads (4 warps 2x2, warp tile 32x32).
// 3-stage cp.async pipeline, ONE __syncthreads per K-tile.
// PARTIAL: gridDim.z=2 splits K; writes raw acc to C + z*M*Nn, no epilogue.
// A and B MUST be pre-rounded to tf32; raw bits feed HMMA.
#define BMg 64
#define BNg 64
#define BKg 32
#define NSTG 3
#define ASTR 36   // BK+4: A frag banks = 4r+cq, conflict-free
#define BSTR 72   // BN+8: B frag banks = 8cq+r, conflict-free
#define A_ELEMS (BMg * ASTR)                 // 2304
#define B_ELEMS (BKg * BSTR)                 // 2304
#define A_BYTES (A_ELEMS * 4)
#define B_BYTES (B_ELEMS * 4)
#define SMEM_BYTES (NSTG * (A_BYTES + B_BYTES))   // 55,296

#define CP16(smem_u32, gptr) \
    asm volatile("cp.async.cg.shared.global [%0], [%1], 16;" :: "r"(smem_u32), "l"(gptr))

template <bool BIAS, bool RES, bool GELU, bool PARTIAL>
__global__ __launch_bounds__(128, 4)
void gemm_tf32(const float* __restrict__ A, const float* __restrict__ B,
               const float* __restrict__ bias, const float* __restrict__ Res,
               float* __restrict__ C, int M, int Nn, int K) {
    extern __shared__ float smem[];
    float* AsBase = smem;                        // [NSTG][BMg][ASTR]
    float* BsBase = smem + NSTG * A_ELEMS;       // [NSTG][BKg][BSTR]

    if (PARTIAL) {
        int kz = blockIdx.z;
        int Kh = K >> 1;
        A += kz * Kh;
        B += (size_t)kz * Kh * Nn;
        C += (size_t)kz * M * Nn;
        K = Kh;
    }

    int tid = threadIdx.x;
    int bm = blockIdx.y * BMg, bn = blockIdx.x * BNg;
    int w = tid >> 5, lane = tid & 31;
    int wm = (w & 1) * 32, wn = (w >> 1) * 32;
    int r = lane >> 2, cq = lane & 3;

    float acc[2][4][4] = {};

    int a_row0 = tid >> 3;
    int a_col  = (tid & 7) * 4;
    int b_row0 = tid >> 4;
    int b_col  = (tid & 15) * 4;

    int niter = K / BKg;

    uint32_t a_sm0[4], b_sm0[4];
#pragma unroll
    for (int j = 0; j < 4; j++) {
        a_sm0[j] = (uint32_t)__cvta_generic_to_shared(AsBase + (a_row0 + j * 16) * ASTR + a_col);
        b_sm0[j] = (uint32_t)__cvta_generic_to_shared(BsBase + (b_row0 + j * 8) * BSTR + b_col);
    }
    const float* Ag = A + (size_t)(bm + a_row0) * K + a_col;
    const float* Bg = B + (size_t)b_row0 * Nn + bn + b_col;
    if (PARTIAL) Ag = A + (size_t)(bm + a_row0) * (K << 1) + a_col;
    size_t a_rstride = PARTIAL ? (size_t)(K << 1) : (size_t)K;

    // prologue: tiles 0,1 -> stages 0,1
#pragma unroll
    for (int t = 0; t < 2; t++) {
        int kt = t * BKg;
#pragma unroll
        for (int j = 0; j < 4; j++)
            CP16(a_sm0[j] + t * A_BYTES, Ag + (size_t)(j * 16) * a_rstride + kt);
#pragma unroll
        for (int j = 0; j < 4; j++)
            CP16(b_sm0[j] + t * B_BYTES, Bg + (size_t)(kt + j * 8) * Nn);
        asm volatile("cp.async.commit_group;");
    }

    int buf = 0, nxt = 2;
    for (int it = 0; it < niter; it++) {
        asm volatile("cp.async.wait_group 1;");
        __syncthreads();
        if (it + 2 < niter) {
            int kt = (it + 2) * BKg;
#pragma unroll
            for (int j = 0; j < 4; j++)
                CP16(a_sm0[j] + nxt * A_BYTES, Ag + (size_t)(j * 16) * a_rstride + kt);
#pragma unroll
            for (int j = 0; j < 4; j++)
                CP16(b_sm0[j] + nxt * B_BYTES, Bg + (size_t)(kt + j * 8) * Nn);
        }
        asm volatile("cp.async.commit_group;");
        nxt = (nxt + 1 == NSTG) ? 0 : nxt + 1;

        const float* Asb = AsBase + buf * A_ELEMS;
        const float* Bsb = BsBase + buf * B_ELEMS;
#pragma unroll
        for (int ks = 0; ks < 4; ks++) {
            int k0 = ks * 8;
            uint32_t af[2][4];
            uint32_t bf[4][2];
#pragma unroll
            for (int mt = 0; mt < 2; mt++) {
                int mb = wm + mt * 16;
                af[mt][0] = __float_as_uint(Asb[(mb + r) * ASTR + k0 + cq]);
                af[mt][1] = __float_as_uint(Asb[(mb + r + 8) * ASTR + k0 + cq]);
                af[mt][2] = __float_as_uint(Asb[(mb + r) * ASTR + k0 + cq + 4]);
                af[mt][3] = __float_as_uint(Asb[(mb + r + 8) * ASTR + k0 + cq + 4]);
            }
#pragma unroll
            for (int nt = 0; nt < 4; nt++) {
                int nb = wn + nt * 8;
                bf[nt][0] = __float_as_uint(Bsb[(k0 + cq) * BSTR + nb + r]);
                bf[nt][1] = __float_as_uint(Bsb[(k0 + cq + 4) * BSTR + nb + r]);
            }
#pragma unroll
            for (int mt = 0; mt < 2; mt++)
#pragma unroll
                for (int nt = 0; nt < 4; nt++) {
                    asm volatile(
                        "mma.sync.aligned.m16n8k8.row.col.f32.tf32.tf32.f32 "
                        "{%0,%1,%2,%3}, {%4,%5,%6,%7}, {%8,%9}, {%0,%1,%2,%3};"
                        : "+f"(acc[mt][nt][0]), "+f"(acc[mt][nt][1]),
                          "+f"(acc[mt][nt][2]), "+f"(acc[mt][nt][3])
                        : "r"(af[mt][0]), "r"(af[mt][1]), "r"(af[mt][2]), "r"(af[mt][3]),
                          "r"(bf[nt][0]), "r"(bf[nt][1]));
                }
        }
        buf = (buf + 1 == NSTG) ? 0 : buf + 1;
    }

    // epilogue
#pragma unroll
    for (int mt = 0; mt < 2; mt++) {
#pragma unroll
        for (int nt = 0; nt < 4; nt++) {
            int row0 = bm + wm + mt * 16 + r;
            int col  = bn + wn + nt * 8 + 2 * cq;
            float v[4] = {acc[mt][nt][0], acc[mt][nt][1], acc[mt][nt][2], acc[mt][nt][3]};
            if (BIAS) {
                float b0 = bias[col], b1 = bias[col + 1];
                v[0] += b0; v[1] += b1; v[2] += b0; v[3] += b1;
            }
            if (GELU) {
#pragma unroll
                for (int q = 0; q < 4; q++) {
                    float gv = v[q] * 0.5f * (1.0f + erff(v[q] * 0.70710678118654752f));
                    v[q] = roundtf(gv);
                }
            }
            if (RES) {
                const float* r0 = Res + (size_t)row0 * Nn + col;
                const float* r1 = Res + (size_t)(row0 + 8) * Nn + col;
                v[0] += r0[0]; v[1] += r0[1]; v[2] += r1[0]; v[3] += r1[1];
            }
            *(float2*)(C + (size_t)row0 * Nn + col)       = make_float2(v[0], v[1]);
            *(float2*)(C + (size_t)(row0 + 8) * Nn + col) = make_float2(v[2], v[3]);
        }
    }
}

// ---------------- 5) attention: one block per (n, head); output pre-rounded ----------------
__global__ void attn_kernel(const float* __restrict__ qkv, float* __restrict__ out) {
    int nb = blockIdx.x;
    int n = nb / HEADS, h = nb % HEADS;
    __shared__ float q[PP][DHEAD + 1];
    __shared__ float k[PP][DHEAD + 1];
    __shared__ float v[PP][DHEAD + 1];
    __shared__ float pr[PP][PP + 1];
    int t = threadIdx.x;
#pragma unroll
    for (int i = 0; i < PP; i++) {
        const float* base = qkv + (size_t)(n * PP + i) * (3 * OUTC) + h * DHEAD;
        q[i][t] = base[t];
        k[i][t] = base[OUTC + t];
        v[i][t] = base[2 * OUTC + t];
    }
    __syncthreads();
    if (t < PP * PP) {
        int i = t / PP, j = t % PP;
        float s = 0.0f;
#pragma unroll
        for (int d = 0; d < DHEAD; d++) s += q[i][d] * k[j][d];
        pr[i][j] = s * 0.125f;
    }
    __syncthreads();
    if (t < PP) {
        float mx = -3.4e38f;
#pragma unroll
        for (int j = 0; j < PP; j++) mx = fmaxf(mx, pr[t][j]);
        float sm = 0.0f;
#pragma unroll
        for (int j = 0; j < PP; j++) { float e = expf(pr[t][j] - mx); pr[t][j] = e; sm += e; }
        float inv = 1.0f / sm;
#pragma unroll
        for (int j = 0; j < PP; j++) pr[t][j] *= inv;
    }
    __syncthreads();
#pragma unroll
    for (int i = 0; i < PP; i++) {
        float o = 0.0f;
#pragma unroll
        for (int j = 0; j < PP; j++) o += pr[i][j] * v[j][t];
        out[(size_t)(n * PP + i) * OUTC + h * DHEAD + t] = roundtf(o);
    }
}

// ---------------- launcher ----------------
extern "C" void kernel_launch(void* const* d_in, const int* in_sizes, int n_in,
                              void* d_out, int out_size) {
    const float* sil    = (const float*)d_in[0];
    const float* pose   = (const float*)d_in[1];
    const int*   mins   = (const int*)  d_in[2];
    const float* ln0_g  = (const float*)d_in[4];
    const float* ln0_b  = (const float*)d_in[5];
    const float* We     = (const float*)d_in[6];
    const float* be     = (const float*)d_in[7];
    const float* ln1_g  = (const float*)d_in[8];
    const float* ln1_b  = (const float*)d_in[9];
    const float* ln_a_g = (const float*)d_in[10];
    const float* ln_a_b = (const float*)d_in[11];
    const float* Wqkv   = (const float*)d_in[12];
    const float* Wo     = (const float*)d_in[13];
    const float* bo     = (const float*)d_in[14];
    const float* ln_f_g = (const float*)d_in[15];
    const float* ln_f_b = (const float*)d_in[16];
    const float* W1     = (const float*)d_in[17];
    const float* b1     = (const float*)d_in[18];
    const float* W2     = (const float*)d_in[19];
    const float* b2     = (const float*)d_in[20];
    float* out = (float*)d_out;

    float *X0, *Xn, *fuse, *qkv, *ao, *ff, *part;
    float *rWe, *rWqkv, *rWo, *rW1, *rW2;
    cudaGetSymbolAddress((void**)&X0,    g_X0);
    cudaGetSymbolAddress((void**)&Xn,    g_Xn);
    cudaGetSymbolAddress((void**)&fuse,  g_fuse);
    cudaGetSymbolAddress((void**)&qkv,   g_qkv);
    cudaGetSymbolAddress((void**)&ao,    g_ao);
    cudaGetSymbolAddress((void**)&ff,    g_ff);
    cudaGetSymbolAddress((void**)&part,  g_part);
    cudaGetSymbolAddress((void**)&rWe,   g_We);
    cudaGetSymbolAddress((void**)&rWqkv, g_Wqkv);
    cudaGetSymbolAddress((void**)&rWo,   g_Wo);
    cudaGetSymbolAddress((void**)&rW1,   g_W1);
    cudaGetSymbolAddress((void**)&rW2,   g_W2);

    cudaFuncSetAttribute(gemm_tf32<false, false, false, true>,  cudaFuncAttributeMaxDynamicSharedMemorySize, SMEM_BYTES);
    cudaFuncSetAttribute(gemm_tf32<false, false, false, false>, cudaFuncAttributeMaxDynamicSharedMemorySize, SMEM_BYTES);
    cudaFuncSetAttribute(gemm_tf32<true,  false, true,  false>, cudaFuncAttributeMaxDynamicSharedMemorySize, SMEM_BYTES);

    // Stage 0: pre-round weights to tf32
    {
        auto rnd = [](const float* src, float* dst, int n) {
            int n4 = n / 4;
            round_tf32_kernel<<<(n4 + 255) / 256, 256>>>(src, dst, n4);
        };
        rnd(We,   rWe,   FUSED * OUTC);
        rnd(Wqkv, rWqkv, DEPTH * OUTC * 3 * OUTC);
        rnd(Wo,   rWo,   DEPTH * OUTC * OUTC);
        rnd(W1,   rW1,   DEPTH * OUTC * FFH);
        rnd(W2,   rW2,   DEPTH * FFH * OUTC);
    }

    // Stage 1: fuse features
    {
        const int R = NB * PP * CC * MAXH;       // 2,523,136, divisible by 64
        pool_kernel<<<R / 64, 256>>>(sil, mins, X0);
    }
    {
        int tot = NB * PP * POSEC * 2;
        pose_kernel<<<(tot + 255) / 256, 256>>>(pose, X0);
    }

    // Stage 2: LN0 -> embed GEMM (split-K) -> combine+LN1 -> LN_a0
    ln_kernel<FUSED, true><<<TOK, 256>>>(X0, Xn, ln0_g, ln0_b);
    gemm_tf32<false, false, false, true><<<dim3(OUTC / BNg, TOK / BMg, 2), 128, SMEM_BYTES>>>(
        Xn, rWe, nullptr, nullptr, part, TOK, OUTC, FUSED);
    ln_combine_kernel<false, true><<<TOK, 256>>>(part, be, nullptr, fuse, nullptr, ln1_g, ln1_b);
    ln_kernel<OUTC, true><<<TOK, 256>>>(fuse, Xn, ln_a_g, ln_a_b);

    // Stage 3: transformer layers
    for (int l = 0; l < DEPTH; l++) {
        gemm_tf32<false, false, false, false><<<dim3(3 * OUTC / BNg, TOK / BMg), 128, SMEM_BYTES>>>(
            Xn, rWqkv + (size_t)l * OUTC * 3 * OUTC, nullptr, nullptr, qkv,
            TOK, 3 * OUTC, OUTC);
        attn_kernel<<<NB * HEADS, 64>>>(qkv, ao);
        gemm_tf32<false, false, false, true><<<dim3(OUTC / BNg, TOK / BMg, 2), 128, SMEM_BYTES>>>(
            ao, rWo + (size_t)l * OUTC * OUTC, nullptr, nullptr, part, TOK, OUTC, OUTC);
        ln_combine_kernel<true, false><<<TOK, 256>>>(
            part, bo + l * OUTC, fuse, fuse, Xn, ln_f_g + l * OUTC, ln_f_b + l * OUTC);
        gemm_tf32<true, false, true, false><<<dim3(FFH / BNg, TOK / BMg), 128, SMEM_BYTES>>>(
            Xn, rW1 + (size_t)l * OUTC * FFH, b1 + l * FFH, nullptr, ff,
            TOK, FFH, OUTC);
        gemm_tf32<false, false, false, true><<<dim3(OUTC / BNg, TOK / BMg, 2), 128, SMEM_BYTES>>>(
            ff, rW2 + (size_t)l * FFH * OUTC, nullptr, nullptr, part, TOK, OUTC, FFH);
        if (l < DEPTH - 1) {
            ln_combine_kernel<true, false><<<TOK, 256>>>(
                part, b2 + l * OUTC, fuse, fuse, Xn,
                ln_a_g + (l + 1) * OUTC, ln_a_b + (l + 1) * OUTC);
        } else {
            final_combine_kernel<<<(TOK * OUTC / 4 + 255) / 256, 256>>>(
                part, b2 + l * OUTC, fuse, out);
        }
    }
}

// round 17
// speedup vs baseline: 1.2907x; 1.2907x over previous
#include <cuda_runtime.h>
#include <cuda_bf16.h>
#include <math.h>
#include <stdint.h>

// ---------------- problem constants ----------------
#define NB     256
#define CC     128
#define HH     77
#define WW     44
#define PP     7
#define MAXH   11
#define POSEC  256
#define VV     17
#define OUTC   512
#define DEPTH  4
#define HEADS  8
#define DHEAD  64
#define FFH    1024
#define FUSED  1920
#define TOK    (NB*PP)       // 1792

// ---------------- scratch (static device memory; no allocation) ----------------
__device__ float g_X0[TOK * FUSED];
__device__ float g_Xn[TOK * FUSED];
__device__ float g_fuse[TOK * OUTC];
__device__ float g_qkv[TOK * 3 * OUTC];
__device__ float g_ao[TOK * OUTC];
__device__ float g_ff[TOK * FFH];
__device__ float g_part[2 * TOK * OUTC];   // split-K partials

__device__ __forceinline__ uint32_t f2tf32(float f) {
    uint32_t u;
    asm("cvt.rna.tf32.f32 %0, %1;" : "=r"(u) : "f"(f));
    return u;
}
__device__ __forceinline__ float roundtf(float f) { return __uint_as_float(f2tf32(f)); }

// ---------------- 1) silhouette pooling (thread-per-row, known good — DO NOT TOUCH) ----------------
__global__ void pool_kernel(const float* __restrict__ sil, const int* __restrict__ mins,
                            float* __restrict__ X0) {
    int idx = blockIdx.x * blockDim.x + threadIdx.x;
    const int total = NB * PP * CC * MAXH;
    if (idx >= total) return;
    int hl = idx % MAXH;
    int c  = (idx / MAXH) % CC;
    int p  = (idx / (MAXH * CC)) % PP;
    int n  = idx / (MAXH * CC * PP);
    int start = mins[p * NB + n];
    start = min(max(start, 0), HH - MAXH);
    int h = start + hl;
    const float4* row = (const float4*)(sil + (((size_t)n * CC + c) * HH + h) * WW);
    float s = 0.0f, mx = -3.4e38f;
#pragma unroll
    for (int w = 0; w < WW / 4; w++) {
        float4 v = row[w];
        s += v.x + v.y + v.z + v.w;
        mx = fmaxf(mx, fmaxf(fmaxf(v.x, v.y), fmaxf(v.z, v.w)));
    }
    X0[((size_t)(n * PP + p)) * FUSED + c * MAXH + hl] = s * (1.0f / WW) + mx;
}

// ---------------- 2) pose binning + leaky relu ----------------
__global__ void pose_kernel(const float* __restrict__ pose, float* __restrict__ X0) {
    int idx = blockIdx.x * blockDim.x + threadIdx.x;
    const int total = NB * PP * POSEC * 2;
    if (idx >= total) return;
    int b  = idx & 1;
    int pc = (idx >> 1) & (POSEC - 1);
    int p  = (idx >> 9) % PP;
    int n  = idx / (PP * POSEC * 2);
    const float* pp = pose + ((size_t)n * POSEC + pc) * VV;
    float v;
    if (p == 0) {
        v = (b == 0) ? (pp[0] + pp[1] + pp[2]) * (1.0f / 3.0f)
                     : (pp[2] + pp[3] + pp[4]) * (1.0f / 3.0f);
    } else {
        v = pp[3 + 2 * p + b];
    }
    v = (v >= 0.0f) ? v : 0.01f * v;
    X0[((size_t)(n * PP + p)) * FUSED + CC * MAXH + pc * 2 + b] = v;
}

// ---------------- 3) LayerNorm (block per row); ROUND pre-rounds output to tf32 ----------------
template <int D, bool ROUND>
__global__ void ln_kernel(const float* __restrict__ X, float* __restrict__ Y,
                          const float* __restrict__ g, const float* __restrict__ b) {
    constexpr int NT = 256;
    constexpr int NE = (D + NT - 1) / NT;
    int row = blockIdx.x;
    const float* x = X + (size_t)row * D;
    float* y = Y + (size_t)row * D;
    int t = threadIdx.x;
    float vals[NE];
    float s = 0.0f, s2 = 0.0f;
#pragma unroll
    for (int e = 0; e < NE; e++) {
        int i = t + e * NT;
        float v = (i < D) ? x[i] : 0.0f;
        vals[e] = v;
        s += v; s2 += v * v;
    }
#pragma unroll
    for (int o = 16; o > 0; o >>= 1) {
        s  += __shfl_xor_sync(0xFFFFFFFFu, s, o);
        s2 += __shfl_xor_sync(0xFFFFFFFFu, s2, o);
    }
    __shared__ float sh[20];
    int wid = t >> 5, lid = t & 31;
    if (lid == 0) { sh[wid] = s; sh[8 + wid] = s2; }
    __syncthreads();
    if (t == 0) {
        float ts = 0.0f, ts2 = 0.0f;
#pragma unroll
        for (int w = 0; w < NT / 32; w++) { ts += sh[w]; ts2 += sh[8 + w]; }
        float m = ts / D;
        float var = ts2 / D - m * m;
        sh[16] = m;
        sh[17] = rsqrtf(var + 1e-5f);
    }
    __syncthreads();
    float m = sh[16], r = sh[17];
#pragma unroll
    for (int e = 0; e < NE; e++) {
        int i = t + e * NT;
        if (i < D) {
            float v = (vals[e] - m) * r * g[i] + b[i];
            y[i] = ROUND ? roundtf(v) : v;
        }
    }
}

// ---------------- 3b) split-K combine + LayerNorm (D = OUTC) ----------------
template <bool HASRES, bool NORMFUSE>
__global__ void ln_combine_kernel(const float* __restrict__ P,
                                  const float* __restrict__ bias,
                                  const float* __restrict__ res,
                                  float* __restrict__ fuse, float* __restrict__ Y,
                                  const float* __restrict__ g, const float* __restrict__ b) {
    constexpr int D = OUTC, NT = 256, NE = 2;
    int row = blockIdx.x;
    const float* p0 = P + (size_t)row * D;
    const float* p1 = P + (size_t)TOK * D + (size_t)row * D;
    int t = threadIdx.x;
    float vals[NE];
    float s = 0.0f, s2 = 0.0f;
#pragma unroll
    for (int e = 0; e < NE; e++) {
        int i = t + e * NT;
        float v = p0[i] + p1[i] + bias[i];
        if (HASRES) v += res[(size_t)row * D + i];
        vals[e] = v;
        s += v; s2 += v * v;
    }
#pragma unroll
    for (int o = 16; o > 0; o >>= 1) {
        s  += __shfl_xor_sync(0xFFFFFFFFu, s, o);
        s2 += __shfl_xor_sync(0xFFFFFFFFu, s2, o);
    }
    __shared__ float sh[20];
    int wid = t >> 5, lid = t & 31;
    if (lid == 0) { sh[wid] = s; sh[8 + wid] = s2; }
    __syncthreads();
    if (t == 0) {
        float ts = 0.0f, ts2 = 0.0f;
#pragma unroll
        for (int w = 0; w < NT / 32; w++) { ts += sh[w]; ts2 += sh[8 + w]; }
        float m = ts / D;
        float var = ts2 / D - m * m;
        sh[16] = m;
        sh[17] = rsqrtf(var + 1e-5f);
    }
    __syncthreads();
    float m = sh[16], r = sh[17];
#pragma unroll
    for (int e = 0; e < NE; e++) {
        int i = t + e * NT;
        float nv = (vals[e] - m) * r * g[i] + b[i];
        if (NORMFUSE) {
            fuse[(size_t)row * D + i] = nv;
        } else {
            fuse[(size_t)row * D + i] = vals[e];
            Y[(size_t)row * D + i]    = roundtf(nv);
        }
    }
}

// ---------------- 3c) final combine: out = P0 + P1 + bias + fuse ----------------
__global__ void final_combine_kernel(const float* __restrict__ P,
                                     const float* __restrict__ bias,
                                     const float* __restrict__ fuse,
                                     float* __restrict__ out) {
    int i4 = blockIdx.x * blockDim.x + threadIdx.x;
    const int total4 = TOK * OUTC / 4;
    if (i4 >= total4) return;
    float4 a = ((const float4*)P)[i4];
    float4 c = ((const float4*)(P + (size_t)TOK * OUTC))[i4];
    float4 f = ((const float4*)fuse)[i4];
    const float4 bb = ((const float4*)bias)[i4 & (OUTC / 4 - 1)];
    float4 o;
    o.x = a.x + c.x + bb.x + f.x;
    o.y = a.y + c.y + bb.y + f.y;
    o.z = a.z + c.z + bb.z + f.z;
    o.w = a.w + c.w + bb.w + f.w;
    ((float4*)out)[i4] = o;
}

// ---------------- 4) tf32 tensor-core GEMM (round-11 core) ----------------
// BM=64, BN=64, BK=32, 128 threads (4 warps 2x2, warp tile 32x32).
// 3-stage cp.async pipeline, ONE __syncthreads per K-tile.
// PARTIAL: gridDim.z=2 splits K; writes raw acc to C + z*M*Nn, no epilogue.
// A must be pre-rounded to tf32 by its producer; B (weights) is rounded on the
// fragment-load path via cvt.rna (bit-identical to pre-rounding, no prep pass).
#define BMg 64
#define BNg 64
#define BKg 32
#define NSTG 3
#define ASTR 36   // BK+4: A frag banks = 4r+cq, conflict-free
#define BSTR 72   // BN+8: B frag banks = 8cq+r, conflict-free
#define A_ELEMS (BMg * ASTR)                 // 2304
#define B_ELEMS (BKg * BSTR)                 // 2304
#define A_BYTES (A_ELEMS * 4)
#define B_BYTES (B_ELEMS * 4)
#define SMEM_BYTES (NSTG * (A_BYTES + B_BYTES))   // 55,296

#define CP16(smem_u32, gptr) \
    asm volatile("cp.async.cg.shared.global [%0], [%1], 16;" :: "r"(smem_u32), "l"(gptr))

template <bool BIAS, bool RES, bool GELU, bool PARTIAL>
__global__ __launch_bounds__(128, 4)
void gemm_tf32(const float* __restrict__ A, const float* __restrict__ B,
               const float* __restrict__ bias, const float* __restrict__ Res,
               float* __restrict__ C, int M, int Nn, int K) {
    extern __shared__ float smem[];
    float* AsBase = smem;                        // [NSTG][BMg][ASTR]
    float* BsBase = smem + NSTG * A_ELEMS;       // [NSTG][BKg][BSTR]

    if (PARTIAL) {
        int kz = blockIdx.z;
        int Kh = K >> 1;
        A += kz * Kh;
        B += (size_t)kz * Kh * Nn;
        C += (size_t)kz * M * Nn;
        K = Kh;
    }

    int tid = threadIdx.x;
    int bm = blockIdx.y * BMg, bn = blockIdx.x * BNg;
    int w = tid >> 5, lane = tid & 31;
    int wm = (w & 1) * 32, wn = (w >> 1) * 32;
    int r = lane >> 2, cq = lane & 3;

    float acc[2][4][4] = {};

    int a_row0 = tid >> 3;
    int a_col  = (tid & 7) * 4;
    int b_row0 = tid >> 4;
    int b_col  = (tid & 15) * 4;

    int niter = K / BKg;

    uint32_t a_sm0[4], b_sm0[4];
#pragma unroll
    for (int j = 0; j < 4; j++) {
        a_sm0[j] = (uint32_t)__cvta_generic_to_shared(AsBase + (a_row0 + j * 16) * ASTR + a_col);
        b_sm0[j] = (uint32_t)__cvta_generic_to_shared(BsBase + (b_row0 + j * 8) * BSTR + b_col);
    }
    const float* Ag = A + (size_t)(bm + a_row0) * K + a_col;
    const float* Bg = B + (size_t)b_row0 * Nn + bn + b_col;
    if (PARTIAL) Ag = A + (size_t)(bm + a_row0) * (K << 1) + a_col;
    size_t a_rstride = PARTIAL ? (size_t)(K << 1) : (size_t)K;

    // prologue: tiles 0,1 -> stages 0,1
#pragma unroll
    for (int t = 0; t < 2; t++) {
        int kt = t * BKg;
#pragma unroll
        for (int j = 0; j < 4; j++)
            CP16(a_sm0[j] + t * A_BYTES, Ag + (size_t)(j * 16) * a_rstride + kt);
#pragma unroll
        for (int j = 0; j < 4; j++)
            CP16(b_sm0[j] + t * B_BYTES, Bg + (size_t)(kt + j * 8) * Nn);
        asm volatile("cp.async.commit_group;");
    }

    int buf = 0, nxt = 2;
    for (int it = 0; it < niter; it++) {
        asm volatile("cp.async.wait_group 1;");
        __syncthreads();
        if (it + 2 < niter) {
            int kt = (it + 2) * BKg;
#pragma unroll
            for (int j = 0; j < 4; j++)
                CP16(a_sm0[j] + nxt * A_BYTES, Ag + (size_t)(j * 16) * a_rstride + kt);
#pragma unroll
            for (int j = 0; j < 4; j++)
                CP16(b_sm0[j] + nxt * B_BYTES, Bg + (size_t)(kt + j * 8) * Nn);
        }
        asm volatile("cp.async.commit_group;");
        nxt = (nxt + 1 == NSTG) ? 0 : nxt + 1;

        const float* Asb = AsBase + buf * A_ELEMS;
        const float* Bsb = BsBase + buf * B_ELEMS;
#pragma unroll
        for (int ks = 0; ks < 4; ks++) {
            int k0 = ks * 8;
            uint32_t af[2][4];
            uint32_t bf[4][2];
#pragma unroll
            for (int mt = 0; mt < 2; mt++) {
                int mb = wm + mt * 16;
                af[mt][0] = __float_as_uint(Asb[(mb + r) * ASTR + k0 + cq]);
                af[mt][1] = __float_as_uint(Asb[(mb + r + 8) * ASTR + k0 + cq]);
                af[mt][2] = __float_as_uint(Asb[(mb + r) * ASTR + k0 + cq + 4]);
                af[mt][3] = __float_as_uint(Asb[(mb + r + 8) * ASTR + k0 + cq + 4]);
            }
#pragma unroll
            for (int nt = 0; nt < 4; nt++) {
                int nb = wn + nt * 8;
                bf[nt][0] = f2tf32(Bsb[(k0 + cq) * BSTR + nb + r]);
                bf[nt][1] = f2tf32(Bsb[(k0 + cq + 4) * BSTR + nb + r]);
            }
#pragma unroll
            for (int mt = 0; mt < 2; mt++)
#pragma unroll
                for (int nt = 0; nt < 4; nt++) {
                    asm volatile(
                        "mma.sync.aligned.m16n8k8.row.col.f32.tf32.tf32.f32 "
                        "{%0,%1,%2,%3}, {%4,%5,%6,%7}, {%8,%9}, {%0,%1,%2,%3};"
                        : "+f"(acc[mt][nt][0]), "+f"(acc[mt][nt][1]),
                          "+f"(acc[mt][nt][2]), "+f"(acc[mt][nt][3])
                        : "r"(af[mt][0]), "r"(af[mt][1]), "r"(af[mt][2]), "r"(af[mt][3]),
                          "r"(bf[nt][0]), "r"(bf[nt][1]));
                }
        }
        buf = (buf + 1 == NSTG) ? 0 : buf + 1;
    }

    // epilogue
#pragma unroll
    for (int mt = 0; mt < 2; mt++) {
#pragma unroll
        for (int nt = 0; nt < 4; nt++) {
            int row0 = bm + wm + mt * 16 + r;
            int col  = bn + wn + nt * 8 + 2 * cq;
            float v[4] = {acc[mt][nt][0], acc[mt][nt][1], acc[mt][nt][2], acc[mt][nt][3]};
            if (BIAS) {
                float b0 = bias[col], b1 = bias[col + 1];
                v[0] += b0; v[1] += b1; v[2] += b0; v[3] += b1;
            }
            if (GELU) {
#pragma unroll
                for (int q = 0; q < 4; q++) {
                    float gv = v[q] * 0.5f * (1.0f + erff(v[q] * 0.70710678118654752f));
                    v[q] = roundtf(gv);   // feeds next GEMM's A operand
                }
            }
            if (RES) {
                const float* r0 = Res + (size_t)row0 * Nn + col;
                const float* r1 = Res + (size_t)(row0 + 8) * Nn + col;
                v[0] += r0[0]; v[1] += r0[1]; v[2] += r1[0]; v[3] += r1[1];
            }
            *(float2*)(C + (size_t)row0 * Nn + col)       = make_float2(v[0], v[1]);
            *(float2*)(C + (size_t)(row0 + 8) * Nn + col) = make_float2(v[2], v[3]);
        }
    }
}

// ---------------- 5) attention: one block per (n, head); output pre-rounded ----------------
__global__ void attn_kernel(const float* __restrict__ qkv, float* __restrict__ out) {
    int nb = blockIdx.x;
    int n = nb / HEADS, h = nb % HEADS;
    __shared__ float q[PP][DHEAD + 1];
    __shared__ float k[PP][DHEAD + 1];
    __shared__ float v[PP][DHEAD + 1];
    __shared__ float pr[PP][PP + 1];
    int t = threadIdx.x;
#pragma unroll
    for (int i = 0; i < PP; i++) {
        const float* base = qkv + (size_t)(n * PP + i) * (3 * OUTC) + h * DHEAD;
        q[i][t] = base[t];
        k[i][t] = base[OUTC + t];
        v[i][t] = base[2 * OUTC + t];
    }
    __syncthreads();
    if (t < PP * PP) {
        int i = t / PP, j = t % PP;
        float s = 0.0f;
#pragma unroll
        for (int d = 0; d < DHEAD; d++) s += q[i][d] * k[j][d];
        pr[i][j] = s * 0.125f;
    }
    __syncthreads();
    if (t < PP) {
        float mx = -3.4e38f;
#pragma unroll
        for (int j = 0; j < PP; j++) mx = fmaxf(mx, pr[t][j]);
        float sm = 0.0f;
#pragma unroll
        for (int j = 0; j < PP; j++) { float e = expf(pr[t][j] - mx); pr[t][j] = e; sm += e; }
        float inv = 1.0f / sm;
#pragma unroll
        for (int j = 0; j < PP; j++) pr[t][j] *= inv;
    }
    __syncthreads();
#pragma unroll
    for (int i = 0; i < PP; i++) {
        float o = 0.0f;
#pragma unroll
        for (int j = 0; j < PP; j++) o += pr[i][j] * v[j][t];
        out[(size_t)(n * PP + i) * OUTC + h * DHEAD + t] = roundtf(o);
    }
}

// ---------------- launcher ----------------
extern "C" void kernel_launch(void* const* d_in, const int* in_sizes, int n_in,
                              void* d_out, int out_size) {
    const float* sil    = (const float*)d_in[0];
    const float* pose   = (const float*)d_in[1];
    const int*   mins   = (const int*)  d_in[2];
    const float* ln0_g  = (const float*)d_in[4];
    const float* ln0_b  = (const float*)d_in[5];
    const float* We     = (const float*)d_in[6];
    const float* be     = (const float*)d_in[7];
    const float* ln1_g  = (const float*)d_in[8];
    const float* ln1_b  = (const float*)d_in[9];
    const float* ln_a_g = (const float*)d_in[10];
    const float* ln_a_b = (const float*)d_in[11];
    const float* Wqkv   = (const float*)d_in[12];
    const float* Wo     = (const float*)d_in[13];
    const float* bo     = (const float*)d_in[14];
    const float* ln_f_g = (const float*)d_in[15];
    const float* ln_f_b = (const float*)d_in[16];
    const float* W1     = (const float*)d_in[17];
    const float* b1     = (const float*)d_in[18];
    const float* W2     = (const float*)d_in[19];
    const float* b2     = (const float*)d_in[20];
    float* out = (float*)d_out;

    float *X0, *Xn, *fuse, *qkv, *ao, *ff, *part;
    cudaGetSymbolAddress((void**)&X0,    g_X0);
    cudaGetSymbolAddress((void**)&Xn,    g_Xn);
    cudaGetSymbolAddress((void**)&fuse,  g_fuse);
    cudaGetSymbolAddress((void**)&qkv,   g_qkv);
    cudaGetSymbolAddress((void**)&ao,    g_ao);
    cudaGetSymbolAddress((void**)&ff,    g_ff);
    cudaGetSymbolAddress((void**)&part,  g_part);

    cudaFuncSetAttribute(gemm_tf32<false, false, false, true>,  cudaFuncAttributeMaxDynamicSharedMemorySize, SMEM_BYTES);
    cudaFuncSetAttribute(gemm_tf32<false, false, false, false>, cudaFuncAttributeMaxDynamicSharedMemorySize, SMEM_BYTES);
    cudaFuncSetAttribute(gemm_tf32<true,  false, true,  false>, cudaFuncAttributeMaxDynamicSharedMemorySize, SMEM_BYTES);

    // Stage 1: fuse features
    {
        int tot = NB * PP * CC * MAXH;
        pool_kernel<<<(tot + 255) / 256, 256>>>(sil, mins, X0);
    }
    {
        int tot = NB * PP * POSEC * 2;
        pose_kernel<<<(tot + 255) / 256, 256>>>(pose, X0);
    }

    // Stage 2: LN0 -> embed GEMM (split-K) -> combine+LN1 -> LN_a0
    ln_kernel<FUSED, true><<<TOK, 256>>>(X0, Xn, ln0_g, ln0_b);
    gemm_tf32<false, false, false, true><<<dim3(OUTC / BNg, TOK / BMg, 2), 128, SMEM_BYTES>>>(
        Xn, We, nullptr, nullptr, part, TOK, OUTC, FUSED);
    ln_combine_kernel<false, true><<<TOK, 256>>>(part, be, nullptr, fuse, nullptr, ln1_g, ln1_b);
    ln_kernel<OUTC, true><<<TOK, 256>>>(fuse, Xn, ln_a_g, ln_a_b);

    // Stage 3: transformer layers
    for (int l = 0; l < DEPTH; l++) {
        gemm_tf32<false, false, false, false><<<dim3(3 * OUTC / BNg, TOK / BMg), 128, SMEM_BYTES>>>(
            Xn, Wqkv + (size_t)l * OUTC * 3 * OUTC, nullptr, nullptr, qkv,
            TOK, 3 * OUTC, OUTC);
        attn_kernel<<<NB * HEADS, 64>>>(qkv, ao);
        gemm_tf32<false, false, false, true><<<dim3(OUTC / BNg, TOK / BMg, 2), 128, SMEM_BYTES>>>(
            ao, Wo + (size_t)l * OUTC * OUTC, nullptr, nullptr, part, TOK, OUTC, OUTC);
        ln_combine_kernel<true, false><<<TOK, 256>>>(
            part, bo + l * OUTC, fuse, fuse, Xn, ln_f_g + l * OUTC, ln_f_b + l * OUTC);
        gemm_tf32<true, false, true, false><<<dim3(FFH / BNg, TOK / BMg), 128, SMEM_BYTES>>>(
            Xn, W1 + (size_t)l * OUTC * FFH, b1 + l * FFH, nullptr, ff,
            TOK, FFH, OUTC);
        gemm_tf32<false, false, false, true><<<dim3(OUTC / BNg, TOK / BMg, 2), 128, SMEM_BYTES>>>(
            ff, W2 + (size_t)l * FFH * OUTC, nullptr, nullptr, part, TOK, OUTC, FFH);
        if (l < DEPTH - 1) {
            ln_combine_kernel<true, false><<<TOK, 256>>>(
                part, b2 + l * OUTC, fuse, fuse, Xn,
                ln_a_g + (l + 1) * OUTC, ln_a_b + (l + 1) * OUTC);
        } else {
            final_combine_kernel<<<(TOK * OUTC / 4 + 255) / 256, 256>>>(
                part, b2 + l * OUTC, fuse, out);
        }
    }
}